// round 9
// baseline (speedup 1.0000x reference)
#include <cuda_runtime.h>
#include <math.h>

// Problem constants
#define LSC   2
#define BSC   16
#define NHC   256
#define NPARTC 512
#define MIDP  256
#define TTC   16
#define DINC  64
#define FHC   1024

// Output layout: tuple (W_mu(16,1), sig(16,1,1), pf(2,16,256,512), wf(16,512), l, nis)
#define OFF_WMU 0
#define OFF_SIG 16
#define OFF_PF  32
#define OFF_WF  (32 + LSC*BSC*NHC*NPARTC)
#define OFF_L   (OFF_WF + BSC*NPARTC)
#define OFF_NIS (OFF_L + 1)

// ---- tiny globals only (33 KB): resample permutation crossing kernels ------
__device__ int g_idx[BSC*2*MIDP];
__device__ int g_do[BSC*2];

__device__ __forceinline__ float sigf(float x)   { return 1.0f/(1.0f+__expf(-x)); }
__device__ __forceinline__ float tanhfa(float x) { return 2.0f/(1.0f+__expf(-2.0f*x)) - 1.0f; }

__device__ __forceinline__ float bsum(float* red, int tid, int nthr, float v){
    red[tid]=v; __syncthreads();
    for (int s=nthr>>1; s>0; s>>=1){ if(tid<s) red[tid]+=red[tid+s]; __syncthreads(); }
    float r = red[0]; __syncthreads(); return r;
}

// =============================================================================
// Persistent LSTM kernel: 128 CTAs x 256 threads. CTA = (batch b, particles
// p0..p0+31). All state (h ping-pong, c) lives in shared memory for all 16
// steps. Writes pr (= final states + noise) directly into pf.
// Shared layout (floats):
//   [0)      Hb: 4 x [32][256]  (h0 parity0/1, h1 parity0/1)   32768
//   [32768)  C0: [32][256]                                      8192
//   [40960)  C1: [32][256]                                      8192
//   [49152)  WT: [16][260]  weight tile                         4160
//   [53312)  XWV: [1024]   permuted input-projection row        1024
//   [54336)  B1P: [1024]   permuted layer-1 bias                1024
//   [55360)  XR:  [64]     x row                                  64
//   total 55424 floats = 221696 bytes
// =============================================================================
#define SMEM_FLOATS 55424
#define SMEM_BYTES  (SMEM_FLOATS*4)

__global__ __launch_bounds__(256)
void k_lstm(const float* __restrict__ x, const float* __restrict__ particles,
            const float* __restrict__ q, const float* __restrict__ e,
            const float* __restrict__ Wih0, const float* __restrict__ Whh0,
            const float* __restrict__ b0,
            const float* __restrict__ Wih1, const float* __restrict__ Whh1,
            const float* __restrict__ b1,
            const float* __restrict__ eps_h, const float* __restrict__ eps_c,
            float* __restrict__ pf){
    extern __shared__ __align__(16) float sm[];
    float* Hb  = sm;
    float* C0  = sm + 32768;
    float* C1  = sm + 40960;
    float* WT  = sm + 49152;
    float* XWV = sm + 53312;
    float* B1P = sm + 54336;
    float* XR  = sm + 55360;

    int tid = threadIdx.x;
    int tx = tid & 63, ty = tid >> 6;      // ty 0..3 -> 8 rows, tx 0..63 -> 1 unit (4 gate cols)
    int blk = blockIdx.x;
    int b = blk >> 3;
    int p0 = (blk & 7) * 32;

    // ---- init: load particle states ----
    for (int idx = tid; idx < 8192; idx += 256){
        int row = idx >> 8, u = idx & 255; int p = p0 + row;
        size_t base0 = ((size_t)(0*BSC + b)*NHC + u)*NPARTC;
        size_t base1 = ((size_t)(1*BSC + b)*NHC + u)*NPARTC;
        Hb[0*8192 + row*256 + u] = particles[base0 + p];
        Hb[2*8192 + row*256 + u] = particles[base1 + p];
        C0[row*256 + u] = particles[base0 + MIDP + p];
        C1[row*256 + u] = particles[base1 + MIDP + p];
    }
    for (int jp = tid; jp < 1024; jp += 256){
        int jo = ((jp & 3) << 8) | (jp >> 2);
        B1P[jp] = b1[jo];
    }
    __syncthreads();

    // ---- time loop ----
    for (int t = 0; t < TTC; t++){
        int cur = t & 1;
        float* h0c = Hb + cur*8192;
        float* h0n = Hb + (cur^1)*8192;
        float* h1c = Hb + (2+cur)*8192;
        float* h1n = Hb + (2+(cur^1))*8192;

        if (tid < 64) XR[tid] = x[(b*TTC + t)*DINC + tid];
        __syncthreads();
        // input projection row for this (b,t), permuted j' = 4u+gate
        for (int jp = tid; jp < 1024; jp += 256){
            int jo = ((jp & 3) << 8) | (jp >> 2);
            const float* wr = Wih0 + jo*DINC;
            float acc = b0[jo];
            #pragma unroll
            for (int k = 0; k < DINC; k++) acc = fmaf(XR[k], wr[k], acc);
            XWV[jp] = acc;
        }
        // (visibility of XWV ensured by the first ktile __syncthreads below)

        for (int layer = 0; layer < 2; layer++){
            const float* Wa = (layer==0) ? Whh0 : Wih1;
            const float* Wb = Whh1;
            const float* Ain0 = (layer==0) ? h0c : h0n;
            const float* Ain1 = h1c;
            float* hout = (layer==0) ? h0n : h1n;
            float* cs   = (layer==0) ? C0 : C1;
            const float* pre = (layer==0) ? XWV : B1P;
            int nkt = (layer==0) ? 16 : 32;

            for (int chunk = 0; chunk < 4; chunk++){
                float4 acc4[8];
                #pragma unroll
                for (int i=0;i<8;i++) acc4[i] = make_float4(0.f,0.f,0.f,0.f);

                for (int kt = 0; kt < nkt; kt++){
                    int khi = (kt >= 16);
                    int k0 = (kt & 15) * 16;
                    const float* Wsrc = khi ? Wb : Wa;
                    const float* Asrc = khi ? Ain1 : Ain0;
                    __syncthreads();   // previous tile consumers done
                    {   // load 16k x 256col tile (thread -> one column)
                        int jp = chunk*256 + tid;
                        int jo = ((jp & 3) << 8) | (jp >> 2);
                        const float* wr = Wsrc + (size_t)jo*256 + k0;
                        #pragma unroll
                        for (int qq=0;qq<4;qq++){
                            float4 w4 = *reinterpret_cast<const float4*>(wr + qq*4);
                            WT[(qq*4+0)*260 + tid] = w4.x;
                            WT[(qq*4+1)*260 + tid] = w4.y;
                            WT[(qq*4+2)*260 + tid] = w4.z;
                            WT[(qq*4+3)*260 + tid] = w4.w;
                        }
                    }
                    __syncthreads();
                    #pragma unroll
                    for (int qq=0;qq<4;qq++){
                        float4 a[8];
                        #pragma unroll
                        for (int i=0;i<8;i++)
                            a[i] = *reinterpret_cast<const float4*>(
                                       &Asrc[(ty*8+i)*256 + k0 + qq*4]);
                        #pragma unroll
                        for (int ee=0;ee<4;ee++){
                            float4 bv = *reinterpret_cast<const float4*>(
                                            &WT[(qq*4+ee)*260 + tx*4]);
                            #pragma unroll
                            for (int i=0;i<8;i++){
                                float av = (ee==0)?a[i].x:(ee==1)?a[i].y:(ee==2)?a[i].z:a[i].w;
                                acc4[i].x = fmaf(av, bv.x, acc4[i].x);
                                acc4[i].y = fmaf(av, bv.y, acc4[i].y);
                                acc4[i].z = fmaf(av, bv.z, acc4[i].z);
                                acc4[i].w = fmaf(av, bv.w, acc4[i].w);
                            }
                        }
                    }
                }
                // epilogue: one unit per thread, 8 rows
                int u = chunk*64 + tx;
                float4 p4 = *reinterpret_cast<const float4*>(&pre[chunk*256 + tx*4]);
                #pragma unroll
                for (int i=0;i<8;i++){
                    int row = ty*8 + i;
                    float gi = acc4[i].x + p4.x;
                    float gf = acc4[i].y + p4.y;
                    float gg = acc4[i].z + p4.z;
                    float go = acc4[i].w + p4.w;
                    float cold = cs[row*256 + u];
                    float cn = sigf(gf)*cold + sigf(gi)*tanhfa(gg);
                    float hn = sigf(go)*tanhfa(cn);
                    cs[row*256 + u]   = cn;
                    hout[row*256 + u] = hn;
                }
            }
        }
        __syncthreads();   // h1n/XWV settled before next t reuses buffers
    }

    // ---- write pr = final state + noise into pf (l,b,u,512) ----
    float sq = sqrtf(q[0]*q[0]);
    float se = sqrtf(e[0]*e[0]);
    const float* h0f = Hb + 0;        // final parity = 0 after 16 steps
    const float* h1f = Hb + 2*8192;
    for (int idx = tid; idx < 8192; idx += 256){
        int row = idx >> 8, u = idx & 255; int p = p0 + row;
        size_t o0 = ((size_t)(0*BSC + b)*NHC + u)*NPARTC;
        size_t o1 = ((size_t)(1*BSC + b)*NHC + u)*NPARTC;
        int e0 = ((p*LSC + 0)*BSC + b)*NHC + u;
        int e1 = ((p*LSC + 1)*BSC + b)*NHC + u;
        pf[o0 + p]          = h0f[row*256+u] + sq*eps_h[e0];
        pf[o1 + p]          = h1f[row*256+u] + sq*eps_h[e1];
        pf[o0 + MIDP + p]   = C0[row*256+u]  + se*eps_c[e0];
        pf[o1 + MIDP + p]   = C1[row*256+u]  + se*eps_c[e1];
    }
}

// =============================================================================
// Single-block stats: obs + weight update + batch-axis norm + resample (wf,idx)
// =============================================================================
__global__ __launch_bounds__(512)
void k_stats(const float* __restrict__ weights, const float* __restrict__ y,
             const float* __restrict__ r, const float* __restrict__ gumbel,
             const float* __restrict__ pf, const float* __restrict__ Wh,
             const float* __restrict__ bh, float* __restrict__ out){
    __shared__ float preWs[16*512];
    __shared__ float red[512];
    __shared__ float key[512];
    __shared__ int   idxs[512];
    int tid = threadIdx.x;
    float rv = r[0];

    for (int b=0;b<16;b++){
        float acc = bh[0];
        const float* base = pf + ((size_t)(BSC + b)*NHC)*NPARTC;   // l=1
        for (int u=0;u<NHC;u++) acc = fmaf(Wh[u], base[(size_t)u*NPARTC + tid], acc);
        float w = logf(weights[b*NPARTC + tid]);
        float wsum = bsum(red, tid, 512, w);
        float s1   = bsum(red, tid, 512, acc*w);
        float Wmu  = s1 / wsum;
        float cen  = acc - Wmu;
        float cov  = bsum(red, tid, 512, cen*cen)/511.0f + rv*rv;
        float s    = cov + 1e-6f;
        float innov = y[b] - acc*w/wsum;
        preWs[b*512 + tid] = w - 0.5f*logf(s) - 0.5f*innov*innov/s;
        __syncthreads();
    }
    // normalize across BATCH axis (reference quirk), then exp
    {
        float ssum = 0.f;
        for (int b=0;b<16;b++) ssum += expf(preWs[b*512 + tid]);
        float ls = logf(ssum);
        for (int b=0;b<16;b++) preWs[b*512 + tid] = expf(preWs[b*512 + tid] - ls);
    }
    __syncthreads();

    // resample: both halves in parallel (tid<256: half0, else half1)
    int half = tid >> 8, j = tid & 255;
    for (int b=0;b<16;b++){
        float wh = preWs[b*512 + half*256 + j];
        red[tid] = wh*wh; __syncthreads();
        for (int s2=128;s2>0;s2>>=1){ if (j < s2) red[tid] += red[tid+s2]; __syncthreads(); }
        float ss = red[half*256];
        __syncthreads();
        int dof = (1.0f/ss < (float)NPARTC/4.0f) ? 1 : 0;
        float soft = 0.5f*wh + 0.5f/256.0f;
        key[tid]  = -(logf(soft) + gumbel[(b*2 + half)*256 + j]);
        idxs[tid] = j;
        __syncthreads();
        for (int k=2;k<=256;k<<=1){
            for (int jj=k>>1;jj>0;jj>>=1){
                int ixj = tid ^ jj;   // stays within half (jj<256, halves 256-aligned)
                if (ixj > tid){
                    bool up = ((j & k) == 0);
                    float a = key[tid], bk = key[ixj];
                    if ((a > bk) == up){
                        key[tid]=bk; key[ixj]=a;
                        int t0=idxs[tid]; idxs[tid]=idxs[ixj]; idxs[ixj]=t0;
                    }
                }
                __syncthreads();
            }
        }
        g_idx[(b*2+half)*256 + j] = idxs[tid];
        float lw = logf(wh/soft);
        red[tid] = lw; __syncthreads();
        for (int s2=128;s2>0;s2>>=1){ if (j<s2) red[tid] = fmaxf(red[tid], red[tid+s2]); __syncthreads(); }
        float mx = red[half*256]; __syncthreads();
        red[tid] = expf(lw - mx); __syncthreads();
        for (int s2=128;s2>0;s2>>=1){ if (j<s2) red[tid] += red[tid+s2]; __syncthreads(); }
        float lse = mx + logf(red[half*256]); __syncthreads();
        float wr = expf(lw - lse);
        out[OFF_WF + b*NPARTC + half*256 + j] = dof ? wr : wh;
        if (j==0) g_do[b*2+half] = dof;
        __syncthreads();
    }
}

// =============================================================================
// In-place gather on pf (per (b,half) permutation), multi-block
// =============================================================================
__global__ __launch_bounds__(256)
void k_gather(float* __restrict__ pf){
    __shared__ __align__(16) float seg[8][256];
    __shared__ int idx_s[256];
    int blk = blockIdx.x;            // b*2+half
    int chunk = blockIdx.y;          // 0..63 -> 8 (l,u) rows each
    int b = blk>>1; int half = blk&1; int tid = threadIdx.x;
    if (!g_do[blk]) return;
    idx_s[tid] = g_idx[blk*MIDP + tid];
    int row0 = chunk*8;
    #pragma unroll
    for (int i=0;i<8;i++){
        int rr = row0 + i;
        int l = rr >> 8, u = rr & 255;
        seg[i][tid] = pf[(((size_t)(l*BSC+b))*NHC + u)*NPARTC + half*MIDP + tid];
    }
    __syncthreads();
    #pragma unroll
    for (int i=0;i<8;i++){
        int rr = row0 + i;
        int l = rr >> 8, u = rr & 255;
        pf[(((size_t)(l*BSC+b))*NHC + u)*NPARTC + half*MIDP + tid] = seg[i][idx_s[tid]];
    }
}

// =============================================================================
// Final estimate (single block)
// =============================================================================
__global__ __launch_bounds__(512)
void k_stats2(const float* __restrict__ y, const float* __restrict__ r,
              const float* __restrict__ pf, const float* __restrict__ Wh,
              const float* __restrict__ bh, float* __restrict__ out){
    __shared__ float red[512];
    int tid = threadIdx.x;
    float rv = r[0];
    float lacc = 0.f, nacc = 0.f;
    for (int b=0;b<16;b++){
        float acc = bh[0];
        const float* base = pf + ((size_t)(BSC + b)*NHC)*NPARTC;   // l=1
        for (int u=0;u<NHC;u++) acc = fmaf(Wh[u], base[(size_t)u*NPARTC + tid], acc);
        float wv = out[OFF_WF + b*NPARTC + tid];
        float wsum = bsum(red, tid, 512, wv);
        float Wmu  = bsum(red, tid, 512, acc*wv) / wsum;
        float cen  = acc - Wmu;
        float cov  = bsum(red, tid, 512, cen*cen)/511.0f + rv*rv;
        if (tid==0){
            out[OFF_WMU + b] = Wmu;
            out[OFF_SIG + b] = cov;
            float s = cov + 1e-6f;
            float inn = y[b] - Wmu;
            float qf = inn*inn/s;
            lacc += -0.5f*logf(s) - 0.5f*qf;
            nacc += qf;
        }
    }
    if (tid==0){ out[OFF_L] = lacc; out[OFF_NIS] = nacc/16.0f; }
}

// =============================================================================
extern "C" void kernel_launch(void* const* d_in, const int* in_sizes, int n_in,
                              void* d_out, int out_size){
    const float* x        = (const float*)d_in[0];
    const float* y        = (const float*)d_in[1];
    const float* particles= (const float*)d_in[2];
    const float* weights  = (const float*)d_in[3];
    const float* q        = (const float*)d_in[4];
    const float* e        = (const float*)d_in[5];
    const float* r        = (const float*)d_in[6];
    const float* Wih0     = (const float*)d_in[7];
    const float* Whh0     = (const float*)d_in[8];
    const float* b0       = (const float*)d_in[9];
    const float* Wih1     = (const float*)d_in[10];
    const float* Whh1     = (const float*)d_in[11];
    const float* b1       = (const float*)d_in[12];
    const float* Wh       = (const float*)d_in[13];
    const float* bh       = (const float*)d_in[14];
    const float* eps_h    = (const float*)d_in[15];
    const float* eps_c    = (const float*)d_in[16];
    const float* gumbel   = (const float*)d_in[17];
    float* out = (float*)d_out;
    float* pf  = out + OFF_PF;

    static bool attr_set = false;
    if (!attr_set){
        cudaFuncSetAttribute(k_lstm, cudaFuncAttributeMaxDynamicSharedMemorySize, SMEM_BYTES);
        attr_set = true;
    }

    // 1. full recurrence, state in shared; writes pr into pf
    k_lstm<<<128, 256, SMEM_BYTES>>>(x, particles, q, e,
                                     Wih0, Whh0, b0, Wih1, Whh1, b1,
                                     eps_h, eps_c, pf);
    // 2. obs + weight update + norm + resample (writes wf, g_idx, g_do)
    k_stats<<<1, 512>>>(weights, y, r, gumbel, pf, Wh, bh, out);
    // 3. in-place gather pr -> pf
    k_gather<<<dim3(BSC*2, 64), 256>>>(pf);
    // 4. final estimate + scalars
    k_stats2<<<1, 512>>>(y, r, pf, Wh, bh, out);
}